// round 1
// baseline (speedup 1.0000x reference)
#include <cuda_runtime.h>
#include <cuda_bf16.h>

// Problem constants
#define B_TOTAL 262144
#define D 64
#define K 1024
#define TILE_K 128
#define NTHREADS 256

// Output layout (float32, concatenated in reference return order)
#define OFF_ZQ    0
#define OFF_IDX   16777216            // B*D
#define OFF_LOSS  17039360            // + B
#define OFF_CS    17039361            // + 1
#define OFF_ES    17040385            // + K
#define OFF_W     17105921            // + K*D

// Scratch (no cudaMalloc allowed)
__device__ float        g_wsq[K];
__device__ unsigned int g_counts[K];
__device__ float        g_embed[K * D];
__device__ float        g_loss;
__device__ float        g_n;

__device__ __forceinline__ void red_add_v4(float* p, float4 v) {
    asm volatile("red.global.add.v4.f32 [%0], {%1,%2,%3,%4};"
                 :: "l"(p), "f"(v.x), "f"(v.y), "f"(v.z), "f"(v.w) : "memory");
}

// -------- zero scratch --------
__global__ void vq_zero() {
    int i = blockIdx.x * blockDim.x + threadIdx.x;   // 256 blocks * 256 = 65536
    if (i < K * D) g_embed[i] = 0.0f;
    if (i < K)     g_counts[i] = 0u;
    if (i == 0)    g_loss = 0.0f;
}

// -------- ||w_k||^2 --------
__global__ void vq_wsq(const float* __restrict__ weight) {
    int k = blockIdx.x * blockDim.x + threadIdx.x;
    if (k >= K) return;
    const float4* wp = (const float4*)(weight + (size_t)k * D);
    float s = 0.0f;
#pragma unroll
    for (int i = 0; i < D / 4; i++) {
        float4 w = wp[i];
        s = fmaf(w.x, w.x, s);
        s = fmaf(w.y, w.y, s);
        s = fmaf(w.z, w.z, s);
        s = fmaf(w.w, w.w, s);
    }
    g_wsq[k] = s;
}

// -------- main: argmin + gather + partial segment sums + loss --------
__global__ __launch_bounds__(NTHREADS)
void vq_main(const float* __restrict__ z,
             const float* __restrict__ weight,
             float* __restrict__ out_zq,
             float* __restrict__ out_idx) {
    __shared__ float sW[TILE_K * D];      // 32 KB
    __shared__ float sWsq[TILE_K];
    __shared__ unsigned int sHist[K];     // 4 KB
    __shared__ float sRed[NTHREADS];

    const int row = blockIdx.x * NTHREADS + threadIdx.x;   // exactly B_TOTAL rows

    // load z row into registers (16 x float4)
    float4 zv[D / 4];
    {
        const float4* zp = (const float4*)(z + (size_t)row * D);
#pragma unroll
        for (int i = 0; i < D / 4; i++) zv[i] = zp[i];
    }

    // zero shared histogram
    for (int i = threadIdx.x; i < K; i += NTHREADS) sHist[i] = 0u;

    float best = 3.4e38f;
    int   bidx = 0;

    for (int t = 0; t < K; t += TILE_K) {
        // cooperative tile load
        {
            const float4* wp = (const float4*)(weight + (size_t)t * D);
            float4* sp = (float4*)sW;
            for (int i = threadIdx.x; i < TILE_K * D / 4; i += NTHREADS) sp[i] = wp[i];
            for (int i = threadIdx.x; i < TILE_K; i += NTHREADS) sWsq[i] = g_wsq[t + i];
        }
        __syncthreads();

        for (int k = 0; k < TILE_K; k++) {
            const float4* wrow = (const float4*)(sW + k * D);
            float dot = 0.0f;
#pragma unroll
            for (int i = 0; i < D / 4; i++) {
                float4 w = wrow[i];
                dot = fmaf(zv[i].x, w.x, dot);
                dot = fmaf(zv[i].y, w.y, dot);
                dot = fmaf(zv[i].z, w.z, dot);
                dot = fmaf(zv[i].w, w.w, dot);
            }
            float score = fmaf(-2.0f, dot, sWsq[k]);   // d2 - z2 (z2 constant per row)
            if (score < best) { best = score; bidx = t + k; }
        }
        __syncthreads();
    }

    // histogram
    atomicAdd(&sHist[bidx], 1u);

    // z2 for loss: ||z - w||^2 = z2 + (w2 - 2 z.w) = z2 + best
    float z2 = 0.0f;
#pragma unroll
    for (int i = 0; i < D / 4; i++) {
        z2 = fmaf(zv[i].x, zv[i].x, z2);
        z2 = fmaf(zv[i].y, zv[i].y, z2);
        z2 = fmaf(zv[i].z, zv[i].z, z2);
        z2 = fmaf(zv[i].w, zv[i].w, z2);
    }
    float dist2 = z2 + best;
    if (dist2 < 0.0f) dist2 = 0.0f;

    // gather z_q = weight[bidx] (L2-hot), write output
    {
        const float4* wb = (const float4*)(weight + (size_t)bidx * D);
        float4* op = (float4*)(out_zq + (size_t)row * D);
#pragma unroll
        for (int i = 0; i < D / 4; i++) op[i] = wb[i];
    }
    out_idx[row] = (float)bidx;

    // embed_sum partials (vector reductions to L2)
    {
        float* eb = g_embed + (size_t)bidx * D;
#pragma unroll
        for (int i = 0; i < D / 4; i++) red_add_v4(eb + 4 * i, zv[i]);
    }

    // block-reduce loss
    sRed[threadIdx.x] = dist2;
    __syncthreads();
#pragma unroll
    for (int s = NTHREADS / 2; s > 0; s >>= 1) {
        if (threadIdx.x < s) sRed[threadIdx.x] += sRed[threadIdx.x + s];
        __syncthreads();
    }
    if (threadIdx.x == 0) atomicAdd(&g_loss, sRed[0]);

    // flush histogram
    for (int i = threadIdx.x; i < K; i += NTHREADS) {
        unsigned int c = sHist[i];
        if (c) atomicAdd(&g_counts[i], c);
    }
}

// -------- finalize A: new_cs, n, vq_loss --------
__global__ void vq_finalA(const float* __restrict__ ema_cs, float* __restrict__ out) {
    __shared__ float sSum[K];
    int k = threadIdx.x;   // 1024 threads
    float ncs = fmaf(0.99f, ema_cs[k], 0.01f * (float)g_counts[k]);
    out[OFF_CS + k] = ncs;
    sSum[k] = ncs;
    __syncthreads();
#pragma unroll
    for (int s = K / 2; s > 0; s >>= 1) {
        if (k < s) sSum[k] += sSum[k + s];
        __syncthreads();
    }
    if (k == 0) {
        g_n = sSum[0];
        out[OFF_LOSS] = 0.25f * g_loss / (float)(B_TOTAL * D);
    }
}

// -------- finalize B: new_es, new_weight --------
__global__ void vq_finalB(const float* __restrict__ ema_es,
                          const float* __restrict__ ema_cs,
                          float* __restrict__ out) {
    int i = blockIdx.x * blockDim.x + threadIdx.x;   // 0 .. K*D-1
    if (i >= K * D) return;
    int k = i >> 6;
    float nes = fmaf(0.99f, ema_es[i], 0.01f * g_embed[i]);
    out[OFF_ES + i] = nes;
    float ncs = fmaf(0.99f, ema_cs[k], 0.01f * (float)g_counts[k]);
    float n = g_n;
    float smoothed = (ncs + 1e-5f) / (n + (float)(K) * 1e-5f) * n;
    out[OFF_W + i] = nes / smoothed;
}

extern "C" void kernel_launch(void* const* d_in, const int* in_sizes, int n_in,
                              void* d_out, int out_size) {
    const float* z      = (const float*)d_in[0];
    const float* weight = (const float*)d_in[1];
    const float* ema_cs = (const float*)d_in[2];
    const float* ema_es = (const float*)d_in[3];
    float* out = (float*)d_out;

    vq_zero<<<(K * D + 255) / 256, 256>>>();
    vq_wsq<<<(K + 255) / 256, 256>>>(weight);
    vq_main<<<B_TOTAL / NTHREADS, NTHREADS>>>(z, weight, out + OFF_ZQ, out + OFF_IDX);
    vq_finalA<<<1, K>>>(ema_cs, out);
    vq_finalB<<<(K * D + 255) / 256, 256>>>(ema_es, ema_cs, out);
}

// round 3
// speedup vs baseline: 2.6760x; 2.6760x over previous
#include <cuda_runtime.h>
#include <cuda_bf16.h>
#include <cstdint>

// ---------------- problem constants ----------------
#define B_TOTAL 262144
#define D 64
#define K 1024
#define M_CTA 256            // rows per CTA
#define NT 256               // threads per CTA
#define PITCH 72             // bf16 elems per smem row (144B; stride%32words==4 -> conflict-free B frags)

// Output layout (float32, reference return order)
#define OFF_ZQ    0
#define OFF_IDX   16777216            // B*D
#define OFF_LOSS  17039360            // + B
#define OFF_CS    17039361            // + 1
#define OFF_ES    17040385            // + K
#define OFF_W     17105921            // + K*D

// ---------------- device scratch (no cudaMalloc allowed) ----------------
__device__ float          g_wsq[K];      // holds -0.5*||w||^2
__device__ unsigned int   g_counts[K];
__device__ float          g_embed[K * D];
__device__ float          g_loss;
__device__ float          g_n;
__device__ __nv_bfloat16  g_wh[K * D];
__device__ __nv_bfloat16  g_wl[K * D];

__device__ __forceinline__ void red_add_v4(float* p, float4 v) {
    asm volatile("red.global.add.v4.f32 [%0], {%1,%2,%3,%4};"
                 :: "l"(p), "f"(v.x), "f"(v.y), "f"(v.z), "f"(v.w) : "memory");
}

__device__ __forceinline__ void mma16816(float c[4], const uint32_t a[4],
                                         uint32_t b0, uint32_t b1) {
    asm volatile("mma.sync.aligned.m16n8k16.row.col.f32.bf16.bf16.f32 "
                 "{%0,%1,%2,%3}, {%4,%5,%6,%7}, {%8,%9}, {%0,%1,%2,%3};"
                 : "+f"(c[0]), "+f"(c[1]), "+f"(c[2]), "+f"(c[3])
                 : "r"(a[0]), "r"(a[1]), "r"(a[2]), "r"(a[3]), "r"(b0), "r"(b1));
}

__device__ __forceinline__ uint32_t pack_hi(float x, float y) {
    __nv_bfloat162 t = __floats2bfloat162_rn(x, y);
    return *(uint32_t*)&t;
}

// ---------------- zero scratch ----------------
__global__ void vq_zero() {
    int i = blockIdx.x * blockDim.x + threadIdx.x;
    if (i < K * D) g_embed[i] = 0.0f;
    if (i < K)     g_counts[i] = 0u;
    if (i == 0)    g_loss = 0.0f;
}

// ---------------- prep: split weights into bf16 hi/lo + (-0.5*w2) ----------------
__global__ void vq_prep(const float* __restrict__ weight) {
    int k = blockIdx.x * blockDim.x + threadIdx.x;
    if (k >= K) return;
    const float4* wp = (const float4*)(weight + (size_t)k * D);
    float s = 0.0f;
    for (int j = 0; j < D / 4; j++) {
        float4 v = wp[j];
        float f[4] = {v.x, v.y, v.z, v.w};
        unsigned short h[4], l[4];
#pragma unroll
        for (int e = 0; e < 4; e++) {
            s = fmaf(f[e], f[e], s);
            __nv_bfloat16 bh = __float2bfloat16_rn(f[e]);
            float fh = __bfloat162float(bh);
            __nv_bfloat16 bl = __float2bfloat16_rn(f[e] - fh);
            h[e] = __bfloat16_as_ushort(bh);
            l[e] = __bfloat16_as_ushort(bl);
        }
        uint2 H, L;
        H.x = (uint32_t)h[0] | ((uint32_t)h[1] << 16);
        H.y = (uint32_t)h[2] | ((uint32_t)h[3] << 16);
        L.x = (uint32_t)l[0] | ((uint32_t)l[1] << 16);
        L.y = (uint32_t)l[2] | ((uint32_t)l[3] << 16);
        ((uint2*)(g_wh + (size_t)k * D))[j] = H;
        ((uint2*)(g_wl + (size_t)k * D))[j] = L;
    }
    g_wsq[k] = -0.5f * s;
}

// ---------------- main fused kernel ----------------
__global__ __launch_bounds__(NT, 2)
void vq_main(const float* __restrict__ z,
             const float* __restrict__ weight,
             float* __restrict__ out_zq,
             float* __restrict__ out_idx) {
    __shared__ __nv_bfloat16 sH[128 * PITCH];   // 18432 B
    __shared__ __nv_bfloat16 sL[128 * PITCH];   // 18432 B
    __shared__ float         sW2n[K];           // -0.5*w2
    __shared__ unsigned int  sHist[K];
    __shared__ int2          sCand[M_CTA];

    const int tid  = threadIdx.x;
    const int wid  = tid >> 5;
    const int lane = tid & 31;
    const int wrb  = wid * 32;                   // warp row base within CTA
    const int row0 = blockIdx.x * M_CTA;

    for (int i = tid; i < K; i += NT) { sW2n[i] = g_wsq[i]; sHist[i] = 0u; }

    // ---- phase 1: stage z (two halves of 128 rows), build A fragments ----
    uint32_t aH[2][4][4], aL[2][4][4];
    const int sr = tid >> 1;                     // staging row this thread fills
    const int sc = (tid & 1) * 32;               // 32 elems per thread
#pragma unroll 1
    for (int h = 0; h < 2; h++) {
        __syncthreads();
        {
            const float4* zp = (const float4*)(z + ((size_t)(row0 + h * 128 + sr)) * D + sc);
            uint2* dH = (uint2*)((char*)sH + sr * (PITCH * 2) + sc * 2);
            uint2* dL = (uint2*)((char*)sL + sr * (PITCH * 2) + sc * 2);
#pragma unroll
            for (int j = 0; j < 8; j++) {
                float4 v = zp[j];
                float f[4] = {v.x, v.y, v.z, v.w};
                unsigned short hh[4], ll[4];
#pragma unroll
                for (int e = 0; e < 4; e++) {
                    __nv_bfloat16 bh = __float2bfloat16_rn(f[e]);
                    float fh = __bfloat162float(bh);
                    __nv_bfloat16 bl = __float2bfloat16_rn(f[e] - fh);
                    hh[e] = __bfloat16_as_ushort(bh);
                    ll[e] = __bfloat16_as_ushort(bl);
                }
                uint2 H, L;
                H.x = (uint32_t)hh[0] | ((uint32_t)hh[1] << 16);
                H.y = (uint32_t)hh[2] | ((uint32_t)hh[3] << 16);
                L.x = (uint32_t)ll[0] | ((uint32_t)ll[1] << 16);
                L.y = (uint32_t)ll[2] | ((uint32_t)ll[3] << 16);
                dH[j] = H; dL[j] = L;
            }
        }
        __syncthreads();
        if ((wid >> 2) == h) {
            const int br = (wid & 3) * 32;
            const char* pH = (const char*)sH;
            const char* pL = (const char*)sL;
#pragma unroll
            for (int f = 0; f < 2; f++)
#pragma unroll
            for (int kk = 0; kk < 4; kk++) {
                int rr = br + f * 16 + (lane >> 2);
                int cb = (kk * 16 + (lane & 3) * 2) * 2;     // byte offset in row
                aH[f][kk][0] = *(const uint32_t*)(pH + rr * 144 + cb);
                aH[f][kk][1] = *(const uint32_t*)(pH + (rr + 8) * 144 + cb);
                aH[f][kk][2] = *(const uint32_t*)(pH + rr * 144 + cb + 16);
                aH[f][kk][3] = *(const uint32_t*)(pH + (rr + 8) * 144 + cb + 16);
                aL[f][kk][0] = *(const uint32_t*)(pL + rr * 144 + cb);
                aL[f][kk][1] = *(const uint32_t*)(pL + (rr + 8) * 144 + cb);
                aL[f][kk][2] = *(const uint32_t*)(pL + rr * 144 + cb + 16);
                aL[f][kk][3] = *(const uint32_t*)(pL + (rr + 8) * 144 + cb + 16);
            }
        }
    }

    // ---- phase 2: stream codebook tiles (128 codes), HMMA, track top-2 ----
    float tb[4], tb2[4];
    int   ti[4], ti2[4];
#pragma unroll
    for (int s = 0; s < 4; s++) { tb[s] = -3.4e38f; tb2[s] = -3.4e38f; ti[s] = 0; ti2[s] = 0; }

#pragma unroll 1
    for (int t = 0; t < K / 128; t++) {
        __syncthreads();
        {
            const uint4* gh = (const uint4*)(g_wh + ((size_t)(t * 128 + sr)) * D + sc);
            const uint4* gl = (const uint4*)(g_wl + ((size_t)(t * 128 + sr)) * D + sc);
            uint4* dh = (uint4*)((char*)sH + sr * 144 + sc * 2);
            uint4* dl = (uint4*)((char*)sL + sr * 144 + sc * 2);
#pragma unroll
            for (int j = 0; j < 4; j++) { dh[j] = gh[j]; dl[j] = gl[j]; }
        }
        __syncthreads();

#pragma unroll 1
        for (int nb = 0; nb < 16; nb++) {
            const int colb = t * 128 + nb * 8 + (lane & 3) * 2;
            float2 w2 = *(const float2*)&sW2n[colb];
            float c0f[4] = {w2.x, w2.y, w2.x, w2.y};
            float c1f[4] = {w2.x, w2.y, w2.x, w2.y};
            const char* bH = (const char*)sH + (nb * 8 + (lane >> 2)) * 144 + (lane & 3) * 4;
            const char* bL = (const char*)sL + (nb * 8 + (lane >> 2)) * 144 + (lane & 3) * 4;
#pragma unroll
            for (int kk = 0; kk < 4; kk++) {
                uint32_t bh0 = *(const uint32_t*)(bH + kk * 32);
                uint32_t bh1 = *(const uint32_t*)(bH + kk * 32 + 16);
                mma16816(c0f, aH[0][kk], bh0, bh1);
                mma16816(c1f, aH[1][kk], bh0, bh1);
                mma16816(c0f, aL[0][kk], bh0, bh1);
                mma16816(c1f, aL[1][kk], bh0, bh1);
                uint32_t bl0 = *(const uint32_t*)(bL + kk * 32);
                uint32_t bl1 = *(const uint32_t*)(bL + kk * 32 + 16);
                mma16816(c0f, aH[0][kk], bl0, bl1);
                mma16816(c1f, aH[1][kk], bl0, bl1);
            }
#define UPD(s, v, ix) do {                                                     \
                float _v = (v); int _ix = (ix);                                \
                if (_v > tb[s]) { tb2[s]=tb[s]; ti2[s]=ti[s]; tb[s]=_v; ti[s]=_ix; } \
                else if (_v > tb2[s]) { tb2[s]=_v; ti2[s]=_ix; }               \
            } while (0)
            UPD(0, c0f[0], colb);  UPD(0, c0f[1], colb + 1);
            UPD(1, c0f[2], colb);  UPD(1, c0f[3], colb + 1);
            UPD(2, c1f[0], colb);  UPD(2, c1f[1], colb + 1);
            UPD(3, c1f[2], colb);  UPD(3, c1f[3], colb + 1);
#undef UPD
        }
    }

    // ---- merge top-2 across the 4 lanes sharing each row ----
#pragma unroll
    for (int s = 0; s < 4; s++) {
#pragma unroll
        for (int off = 1; off <= 2; off <<= 1) {
            float ob  = __shfl_xor_sync(0xffffffffu, tb[s],  off);
            int   oi  = __shfl_xor_sync(0xffffffffu, ti[s],  off);
            float ob2 = __shfl_xor_sync(0xffffffffu, tb2[s], off);
            int   oi2 = __shfl_xor_sync(0xffffffffu, ti2[s], off);
            float cb; int ci;
            if (ob > tb[s]) { cb = tb[s]; ci = ti[s]; tb[s] = ob; ti[s] = oi; }
            else            { cb = ob;    ci = oi; }
            if (cb  > tb2[s]) { tb2[s] = cb;  ti2[s] = ci; }
            if (ob2 > tb2[s]) { tb2[s] = ob2; ti2[s] = oi2; }
        }
        if ((lane & 3) == 0) sCand[wrb + (lane >> 2) + 8 * s] = make_int2(ti[s], ti2[s]);
    }
    __syncthreads();

    // ---- epilogue: one thread per row; exact fp32 re-check of top-2 ----
    {
        const int row = row0 + tid;
        int2 cd = sCand[tid];
        const float4* zp = (const float4*)(z + (size_t)row * D);
        const float4* wa = (const float4*)(weight + (size_t)cd.x * D);
        const float4* wb = (const float4*)(weight + (size_t)cd.y * D);
        float4 zr[D / 4];
        float d2a = 0.0f, d2b = 0.0f;
#pragma unroll
        for (int j = 0; j < D / 4; j++) {
            zr[j] = zp[j];
            float4 a = wa[j], b = wb[j];
            float dx = zr[j].x - a.x, dy = zr[j].y - a.y, dz = zr[j].z - a.z, dw = zr[j].w - a.w;
            d2a = fmaf(dx, dx, d2a); d2a = fmaf(dy, dy, d2a);
            d2a = fmaf(dz, dz, d2a); d2a = fmaf(dw, dw, d2a);
            dx = zr[j].x - b.x; dy = zr[j].y - b.y; dz = zr[j].z - b.z; dw = zr[j].w - b.w;
            d2b = fmaf(dx, dx, d2b); d2b = fmaf(dy, dy, d2b);
            d2b = fmaf(dz, dz, d2b); d2b = fmaf(dw, dw, d2b);
        }
        int widx; float d2;
        if (d2b < d2a || (d2b == d2a && cd.y < cd.x)) { widx = cd.y; d2 = d2b; }
        else                                          { widx = cd.x; d2 = d2a; }

        const float4* wv = (const float4*)(weight + (size_t)widx * D);
        float4* op = (float4*)(out_zq + (size_t)row * D);
        float* eb = g_embed + (size_t)widx * D;
#pragma unroll
        for (int j = 0; j < D / 4; j++) {
            op[j] = wv[j];
            red_add_v4(eb + 4 * j, zr[j]);
        }
        out_idx[row] = (float)widx;
        atomicAdd(&sHist[widx], 1u);

#pragma unroll
        for (int o = 16; o; o >>= 1) d2 += __shfl_xor_sync(0xffffffffu, d2, o);
        if (lane == 0) atomicAdd(&g_loss, d2);
    }
    __syncthreads();
    for (int i = tid; i < K; i += NT) {
        unsigned int c = sHist[i];
        if (c) atomicAdd(&g_counts[i], c);
    }
}

// ---------------- finalize ----------------
__global__ void vq_finalA(const float* __restrict__ ema_cs, float* __restrict__ out) {
    __shared__ float sSum[K];
    int k = threadIdx.x;
    float ncs = fmaf(0.99f, ema_cs[k], 0.01f * (float)g_counts[k]);
    out[OFF_CS + k] = ncs;
    sSum[k] = ncs;
    __syncthreads();
#pragma unroll
    for (int s = K / 2; s > 0; s >>= 1) {
        if (k < s) sSum[k] += sSum[k + s];
        __syncthreads();
    }
    if (k == 0) {
        g_n = sSum[0];
        out[OFF_LOSS] = 0.25f * g_loss / (float)(B_TOTAL * D);
    }
}

__global__ void vq_finalB(const float* __restrict__ ema_es,
                          const float* __restrict__ ema_cs,
                          float* __restrict__ out) {
    int i = blockIdx.x * blockDim.x + threadIdx.x;
    if (i >= K * D) return;
    int k = i >> 6;
    float nes = fmaf(0.99f, ema_es[i], 0.01f * g_embed[i]);
    out[OFF_ES + i] = nes;
    float ncs = fmaf(0.99f, ema_cs[k], 0.01f * (float)g_counts[k]);
    float n = g_n;
    float smoothed = (ncs + 1e-5f) / (n + (float)K * 1e-5f) * n;
    out[OFF_W + i] = nes / smoothed;
}

extern "C" void kernel_launch(void* const* d_in, const int* in_sizes, int n_in,
                              void* d_out, int out_size) {
    const float* z      = (const float*)d_in[0];
    const float* weight = (const float*)d_in[1];
    const float* ema_cs = (const float*)d_in[2];
    const float* ema_es = (const float*)d_in[3];
    float* out = (float*)d_out;

    vq_zero<<<(K * D + 255) / 256, 256>>>();
    vq_prep<<<(K + 127) / 128, 128>>>(weight);
    vq_main<<<B_TOTAL / M_CTA, NT>>>(z, weight, out + OFF_ZQ, out + OFF_IDX);
    vq_finalA<<<1, K>>>(ema_cs, out);
    vq_finalB<<<(K * D + 255) / 256, 256>>>(ema_es, ema_cs, out);
}